// round 9
// baseline (speedup 1.0000x reference)
#include <cuda_runtime.h>
#include <cuda_fp16.h>
#include <math.h>

#define HF 200
#define WF 200
#define CH 256
#define HO 7
#define WO 7
#define SUBS 2
#define HS (HO * SUBS)   // 14
#define WS (WO * SUBS)   // 14

#define ROW_BYTES (WF * CH * 2)   // 102400
#define COL_BYTES (CH * 2)        // 512
#define SPITCH 264                // halves per staged position (256 + 8 pad)
#define NTHR 224
#define SMEM_BYTES (16 * NTHR * 16)   // 57344: stage[16][224] of uint4

// Channels-last fp16 scratch copy: g_featTh[(y*WF + x)*CH + c]  (20.5 MB)
__device__ __align__(16) __half g_featTh[HF * WF * CH];

static __device__ __forceinline__ __half2 u2h2(unsigned u) {
    return *reinterpret_cast<__half2*>(&u);
}

static __device__ __forceinline__ void cp_async16(unsigned dst_smem, const void* src) {
    asm volatile("cp.async.cg.shared.global [%0], [%1], 16;\n"
                 :: "r"(dst_smem), "l"(src) : "memory");
}

// ---------------------------------------------------------------------------
// Kernel 1: transpose (C, H*W) f32 -> (H*W, C) fp16 (HBM-roofline bound)
// ---------------------------------------------------------------------------
__global__ void transpose_kernel(const float* __restrict__ in) {
    __shared__ float tile[32][33];
    const int p0 = blockIdx.x * 32;
    const int c0 = blockIdx.y * 32;
    const int tx = threadIdx.x;
    const int ty = threadIdx.y;

#pragma unroll
    for (int i = 0; i < 32; i += 8) {
        tile[ty + i][tx] = in[(size_t)(c0 + ty + i) * (HF * WF) + (p0 + tx)];
    }
    __syncthreads();

    const int tid = ty * 32 + tx;
#pragma unroll
    for (int it = 0; it < 2; it++) {
        const int idx = tid + it * 256;
        const int p_local = idx >> 4;
        const int k = idx & 15;
        __half2 h = __floats2half2_rn(tile[2 * k][p_local], tile[2 * k + 1][p_local]);
        *(__half2*)&g_featTh[(size_t)(p0 + p_local) * CH + c0 + 2 * k] = h;
    }
}

// ---------------------------------------------------------------------------
// Kernel 2: ROI align + 2x2 max subsample via cp.async staging.
// Grid: (N, 7). Block: 224 threads = 7 pw x 32 c8.
// All 16 corner loads issued as cp.async.cg (fire-and-forget, MLP=16,
// L1-bypass), staged in smem [i][tid] (conflict-free), then computed.
// ---------------------------------------------------------------------------
__global__ __launch_bounds__(NTHR) void roialign_kernel(
    const float* __restrict__ rois,
    const float* __restrict__ img_size,
    float* __restrict__ out)
{
    extern __shared__ __align__(16) unsigned char dsmem[];
    uint4* stage = (uint4*)dsmem;
    const unsigned sbase = (unsigned)__cvta_generic_to_shared(dsmem);

    const int n   = blockIdx.x;
    const int ph  = blockIdx.y;
    const int tid = threadIdx.x;
    const int pw  = tid >> 5;     // 0..6
    const int c8  = tid & 31;     // 0..31

    const float4 roi = __ldg((const float4*)rois + n);
    const float Hi = __ldg(img_size);
    const float Wi = __ldg(img_size + 1);
    const float sy_scale = (HF - 1.0f) / (Hi - 1.0f);
    const float sx_scale = (WF - 1.0f) / (Wi - 1.0f);
    const float r0 = roi.x * sy_scale;
    const float r1 = roi.y * sx_scale;
    const float h_step = (roi.z * sy_scale - r0) * (1.0f / (float)HS);
    const float w_step = (roi.w * sx_scale - r1) * (1.0f / (float)WS);

    // --- per-thread geometry ---
    const float yy0 = ((float)(2 * ph) + 0.5f) * h_step + r0;
    const float yy1 = yy0 + h_step;
    const float xx0 = ((float)(2 * pw) + 0.5f) * w_step + r1;
    const float xx1 = xx0 + w_step;

    const int iy0 = __float2int_rd(yy0);
    const int iy1 = __float2int_rd(yy1);
    const int ix0 = __float2int_rd(xx0);
    const int ix1 = __float2int_rd(xx1);

    const __half2 fy0 = __float2half2_rn(yy0 - (float)iy0);
    const __half2 fy1 = __float2half2_rn(yy1 - (float)iy1);
    const __half2 fx0 = __float2half2_rn(xx0 - (float)ix0);
    const __half2 fx1 = __float2half2_rn(xx1 - (float)ix1);

    const unsigned ru0 = (unsigned)iy0 * ROW_BYTES;
    const unsigned ru1 = (unsigned)iy1 * ROW_BYTES;
    const unsigned rd0 = ru0 + ROW_BYTES;
    const unsigned rd1 = ru1 + ROW_BYTES;
    const unsigned cl0 = (unsigned)ix0 * COL_BYTES;
    const unsigned cl1 = (unsigned)ix1 * COL_BYTES;
    const unsigned cr0 = cl0 + COL_BYTES;
    const unsigned cr1 = cl1 + COL_BYTES;

    const char* fb = (const char*)g_featTh + c8 * 16;

    // --- fire all 16 gathers as cp.async (no dest regs -> guaranteed MLP) ---
    const unsigned offs[16] = {
        ru0 + cl0, ru0 + cr0, rd0 + cl0, rd0 + cr0,
        ru0 + cl1, ru0 + cr1, rd0 + cl1, rd0 + cr1,
        ru1 + cl0, ru1 + cr0, rd1 + cl0, rd1 + cr0,
        ru1 + cl1, ru1 + cr1, rd1 + cl1, rd1 + cr1
    };
#pragma unroll
    for (int i = 0; i < 16; i++) {
        cp_async16(sbase + (unsigned)(i * NTHR + tid) * 16u, fb + offs[i]);
    }
    asm volatile("cp.async.commit_group;\n" ::: "memory");
    asm volatile("cp.async.wait_group 0;\n" ::: "memory");

    // --- compute from smem (own data; no syncthreads needed before read) ---
    __half2 best[4];
    const __half2 ninf = __float2half2_rn(-60000.0f);
#pragma unroll
    for (int j = 0; j < 4; j++) best[j] = ninf;

    const __half2 fxs[4] = {fx0, fx1, fx0, fx1};
    const __half2 fys[4] = {fy0, fy0, fy1, fy1};

#pragma unroll
    for (int s = 0; s < 4; s++) {
        const uint4 vul = stage[(s * 4 + 0) * NTHR + tid];
        const uint4 vur = stage[(s * 4 + 1) * NTHR + tid];
        const uint4 vdl = stage[(s * 4 + 2) * NTHR + tid];
        const uint4 vdr = stage[(s * 4 + 3) * NTHR + tid];
        const unsigned* pul = (const unsigned*)&vul;
        const unsigned* pur = (const unsigned*)&vur;
        const unsigned* pdl = (const unsigned*)&vdl;
        const unsigned* pdr = (const unsigned*)&vdr;
        const __half2 fx2 = fxs[s];
        const __half2 fy2 = fys[s];
#pragma unroll
        for (int j = 0; j < 4; j++) {
            const __half2 ul = u2h2(pul[j]);
            const __half2 ur = u2h2(pur[j]);
            const __half2 dl = u2h2(pdl[j]);
            const __half2 dr = u2h2(pdr[j]);
            const __half2 t = __hfma2(fx2, __hsub2(ur, ul), ul);
            const __half2 b = __hfma2(fx2, __hsub2(dr, dl), dl);
            const __half2 vv = __hfma2(fy2, __hsub2(b, t), t);
            best[j] = __hmax2(best[j], vv);
        }
    }

    // --- stage results (reuse smem; all corner reads are done) ---
    __syncthreads();
    __half* s_half = (__half*)dsmem;
    *(uint4*)&s_half[pw * SPITCH + c8 * 8] = *(const uint4*)best;
    __syncthreads();

    // --- writeback: fixed pw per thread, c += 32 per iter ---
    {
        int c  = tid / 7;
        const int wpw = tid - c * 7;
        const __half* sp = s_half + wpw * SPITCH;
        float* gp = out + (size_t)n * (CH * HO * WO) + (size_t)c * (HO * WO)
                        + ph * WO + wpw;
#pragma unroll
        for (int k = 0; k < 8; k++) {
            *gp = __half2float(sp[c]);
            c  += 32;
            gp += 32 * (HO * WO);
        }
    }
}

extern "C" void kernel_launch(void* const* d_in, const int* in_sizes, int n_in,
                              void* d_out, int out_size) {
    const float* features = (const float*)d_in[0];  // (1, 256, 200, 200)
    const float* rois     = (const float*)d_in[1];  // (512, 4)
    const float* img_size = (const float*)d_in[2];  // (2,)
    float* out = (float*)d_out;                     // (512, 256, 7, 7)

    const int n_rois = in_sizes[1] / 4;

    static int attr_set = 0;
    if (!attr_set) {
        cudaFuncSetAttribute(roialign_kernel,
                             cudaFuncAttributeMaxDynamicSharedMemorySize,
                             SMEM_BYTES);
        attr_set = 1;
    }

    dim3 tgrid(HF * WF / 32, CH / 32);
    dim3 tblock(32, 8);
    transpose_kernel<<<tgrid, tblock>>>(features);

    dim3 rgrid(n_rois, HO);
    roialign_kernel<<<rgrid, NTHR, SMEM_BYTES>>>(rois, img_size, out);
}